// round 1
// baseline (speedup 1.0000x reference)
#include <cuda_runtime.h>
#include <math.h>
#include <stdint.h>

#define S_LEN 8192
#define DIM   1024
#define NH    16
#define HD    64
#define WIN   512

// Scratch buffers (static __device__ allocation is permitted)
__device__ float g_q[S_LEN * DIM];
__device__ float g_k[S_LEN * DIM];
__device__ float g_v[S_LEN * DIM];
__device__ float g_o[S_LEN * DIM];

// ---------------------------------------------------------------------------
// GEMM: C[m][n] = sum_k A[m][k] * B[n][k]   (A: MxK row-major, B: NxK row-major)
// Tiles: BM=128, BN=64, BK=16. 256 threads, 8x4 micro-tile per thread.
// ---------------------------------------------------------------------------
__global__ __launch_bounds__(256) void gemm_abT(
    const float* __restrict__ A, const float* __restrict__ B,
    float* __restrict__ C, int M, int N, int K)
{
    __shared__ float As[16][128];   // [k][m]
    __shared__ float Bs[16][64];    // [k][n]

    const int tid = threadIdx.x;
    const int m0 = blockIdx.x * 128;
    const int n0 = blockIdx.y * 64;
    const int ty = tid >> 4;   // 0..15 -> rows ty*8..ty*8+7
    const int tx = tid & 15;   // 0..15 -> cols tx*4..tx*4+3

    float acc[8][4];
#pragma unroll
    for (int i = 0; i < 8; i++)
#pragma unroll
        for (int j = 0; j < 4; j++) acc[i][j] = 0.f;

    for (int k0 = 0; k0 < K; k0 += 16) {
        // Load A tile (128x16) transposed into As[k][m]
#pragma unroll
        for (int c = 0; c < 2; c++) {
            int f = tid + c * 256;          // 0..511 float4 slots
            int row = f >> 2;               // 0..127
            int kq = (f & 3) << 2;          // 0,4,8,12
            float4 v = *(const float4*)(A + (size_t)(m0 + row) * K + k0 + kq);
            As[kq + 0][row] = v.x;
            As[kq + 1][row] = v.y;
            As[kq + 2][row] = v.z;
            As[kq + 3][row] = v.w;
        }
        // Load B tile (64x16) transposed into Bs[k][n]
        {
            int row = tid >> 2;             // 0..63
            int kq = (tid & 3) << 2;        // 0,4,8,12
            float4 v = *(const float4*)(B + (size_t)(n0 + row) * K + k0 + kq);
            Bs[kq + 0][row] = v.x;
            Bs[kq + 1][row] = v.y;
            Bs[kq + 2][row] = v.z;
            Bs[kq + 3][row] = v.w;
        }
        __syncthreads();

#pragma unroll
        for (int kk = 0; kk < 16; kk++) {
            float4 b4 = *(const float4*)&Bs[kk][tx * 4];
            float4 a0 = *(const float4*)&As[kk][ty * 8];
            float4 a1 = *(const float4*)&As[kk][ty * 8 + 4];
            float a[8] = {a0.x, a0.y, a0.z, a0.w, a1.x, a1.y, a1.z, a1.w};
            float b[4] = {b4.x, b4.y, b4.z, b4.w};
#pragma unroll
            for (int i = 0; i < 8; i++)
#pragma unroll
                for (int j = 0; j < 4; j++)
                    acc[i][j] += a[i] * b[j];
        }
        __syncthreads();
    }

#pragma unroll
    for (int i = 0; i < 8; i++) {
        float4 v = make_float4(acc[i][0], acc[i][1], acc[i][2], acc[i][3]);
        *(float4*)(C + (size_t)(m0 + ty * 8 + i) * N + n0 + tx * 4) = v;
    }
}

// ---------------------------------------------------------------------------
// RoPE on q and k, in place. One thread per (s, pair). Mirrors JAX f32 math.
// ---------------------------------------------------------------------------
__global__ void rope_kernel(float* __restrict__ q, float* __restrict__ k)
{
    int idx = blockIdx.x * blockDim.x + threadIdx.x;
    if (idx >= S_LEN * (DIM / 2)) return;
    int s = idx >> 9;           // 512 pairs per sequence position
    int p = idx & 511;
    int i = p & 31;             // pair index within head (D/2 = 32)
    int h = p >> 5;

    float e = (float)(2 * i) * (1.0f / 64.0f);
    float inv = 1.0f / powf(10000.0f, e);
    float ang = (float)s * inv;
    float sn, cs;
    sincosf(ang, &sn, &cs);

    size_t off = (size_t)s * DIM + (h << 6) + 2 * i;
    float2 qv = *(float2*)(q + off);
    float2 kv = *(float2*)(k + off);
    float2 qo, ko;
    qo.x = qv.x * cs - qv.y * sn;  qo.y = qv.x * sn + qv.y * cs;
    ko.x = kv.x * cs - kv.y * sn;  ko.y = kv.x * sn + kv.y * cs;
    *(float2*)(q + off) = qo;
    *(float2*)(k + off) = ko;
}

// ---------------------------------------------------------------------------
// Sliding-window flash attention.
// Block = (64-query tile, head). 128 threads.
// Key tiles of 32, t = 0..17, kbase = qbase - 512 + 32t (skip kbase < 0).
// Each query attends keys g with max(0, Q-511) <= g <= Q.
// Thread map: ty = tid/8 (4 q-rows ty*4..), tx = tid%8.
//   S-GEMM:  cols tx*4..tx*4+3 (keys)
//   PV-GEMM: cols tx*8..tx*8+7 (dims)   -- same q-rows, so row stats stay local
// ---------------------------------------------------------------------------
__global__ __launch_bounds__(128) void swa_kernel(
    const float* __restrict__ q, const float* __restrict__ k,
    const float* __restrict__ v, float* __restrict__ o)
{
    __shared__ float Qt[64][64];   // [d][qrow]
    __shared__ float Kt[64][32];   // [d][j]
    __shared__ float Vs[32][64];   // [j][d]
    __shared__ float Ps[32][65];   // [j][qrow], padded stride

    const int tid = threadIdx.x;
    const int h = blockIdx.y;
    const int qbase = blockIdx.x * 64;
    const int ty = tid >> 3;   // 0..15
    const int tx = tid & 7;    // 0..7

    // Load Q tile transposed: Qt[d][row]
#pragma unroll
    for (int c = 0; c < 8; c++) {
        int f = tid + c * 128;
        int row = f >> 4;            // 0..63
        int dq = (f & 15) << 2;      // 0..60
        float4 vq = *(const float4*)(q + (size_t)(qbase + row) * DIM + h * HD + dq);
        Qt[dq + 0][row] = vq.x;
        Qt[dq + 1][row] = vq.y;
        Qt[dq + 2][row] = vq.z;
        Qt[dq + 3][row] = vq.w;
    }

    float m[4], l[4], O[4][8];
#pragma unroll
    for (int i = 0; i < 4; i++) {
        m[i] = -1e30f;
        l[i] = 0.f;
#pragma unroll
        for (int d = 0; d < 8; d++) O[i][d] = 0.f;
    }

    for (int t = 0; t < 18; t++) {
        int kbase = qbase - 512 + t * 32;
        if (kbase < 0) continue;   // uniform across block: safe w.r.t. barriers
        __syncthreads();           // protect smem from previous iteration readers

        // Load K (transposed) and V (natural)
#pragma unroll
        for (int c = 0; c < 4; c++) {
            int f = tid + c * 128;
            int j = f >> 4;              // 0..31
            int dq = (f & 15) << 2;      // 0..60
            float4 kv = *(const float4*)(k + (size_t)(kbase + j) * DIM + h * HD + dq);
            Kt[dq + 0][j] = kv.x;
            Kt[dq + 1][j] = kv.y;
            Kt[dq + 2][j] = kv.z;
            Kt[dq + 3][j] = kv.w;
            float4 vv = *(const float4*)(v + (size_t)(kbase + j) * DIM + h * HD + dq);
            *(float4*)&Vs[j][dq] = vv;
        }
        __syncthreads();

        // S = Q K^T   (64 d-steps, 16 FFMA each)
        float s_[4][4];
#pragma unroll
        for (int i = 0; i < 4; i++)
#pragma unroll
            for (int j = 0; j < 4; j++) s_[i][j] = 0.f;
#pragma unroll 16
        for (int d = 0; d < 64; d++) {
            float4 a4 = *(const float4*)&Qt[d][ty * 4];
            float4 b4 = *(const float4*)&Kt[d][tx * 4];
            float a[4] = {a4.x, a4.y, a4.z, a4.w};
            float b[4] = {b4.x, b4.y, b4.z, b4.w};
#pragma unroll
            for (int i = 0; i < 4; i++)
#pragma unroll
                for (int j = 0; j < 4; j++)
                    s_[i][j] += a[i] * b[j];
        }

        // Mask + online softmax; stage P into smem; rescale O
#pragma unroll
        for (int i = 0; i < 4; i++) {
            int qg = qbase + ty * 4 + i;
            float sv[4];
            float rowmax = -1e30f;
#pragma unroll
            for (int j = 0; j < 4; j++) {
                int kg = kbase + tx * 4 + j;
                bool valid = (kg <= qg) && (kg >= qg - (WIN - 1));
                sv[j] = valid ? s_[i][j] * 0.125f : -1e30f;
                rowmax = fmaxf(rowmax, sv[j]);
            }
            rowmax = fmaxf(rowmax, __shfl_xor_sync(0xffffffffu, rowmax, 1));
            rowmax = fmaxf(rowmax, __shfl_xor_sync(0xffffffffu, rowmax, 2));
            rowmax = fmaxf(rowmax, __shfl_xor_sync(0xffffffffu, rowmax, 4));

            float mnew = fmaxf(m[i], rowmax);
            float scale = __expf(m[i] - mnew);   // m==mnew==-1e30 -> exp(0)=1, l stays 0
            float rs = 0.f;
#pragma unroll
            for (int j = 0; j < 4; j++) {
                float pj = (sv[j] > -5e29f) ? __expf(sv[j] - mnew) : 0.f;
                Ps[tx * 4 + j][ty * 4 + i] = pj;
                rs += pj;
            }
            rs += __shfl_xor_sync(0xffffffffu, rs, 1);
            rs += __shfl_xor_sync(0xffffffffu, rs, 2);
            rs += __shfl_xor_sync(0xffffffffu, rs, 4);

            l[i] = l[i] * scale + rs;
            m[i] = mnew;
#pragma unroll
            for (int d = 0; d < 8; d++) O[i][d] *= scale;
        }
        __syncthreads();

        // O += P V   (32 j-steps, 32 FFMA each)
#pragma unroll 8
        for (int j = 0; j < 32; j++) {
            float a0 = Ps[j][ty * 4 + 0];
            float a1 = Ps[j][ty * 4 + 1];
            float a2 = Ps[j][ty * 4 + 2];
            float a3 = Ps[j][ty * 4 + 3];
            float4 b0 = *(const float4*)&Vs[j][tx * 8];
            float4 b1 = *(const float4*)&Vs[j][tx * 8 + 4];
            float b[8] = {b0.x, b0.y, b0.z, b0.w, b1.x, b1.y, b1.z, b1.w};
#pragma unroll
            for (int d = 0; d < 8; d++) {
                O[0][d] += a0 * b[d];
                O[1][d] += a1 * b[d];
                O[2][d] += a2 * b[d];
                O[3][d] += a3 * b[d];
            }
        }
    }

    // Normalize + write out: o[row][h*64 + tx*8 .. +7]
#pragma unroll
    for (int i = 0; i < 4; i++) {
        float inv_l = 1.0f / l[i];
        float4 v0 = make_float4(O[i][0] * inv_l, O[i][1] * inv_l,
                                O[i][2] * inv_l, O[i][3] * inv_l);
        float4 v1 = make_float4(O[i][4] * inv_l, O[i][5] * inv_l,
                                O[i][6] * inv_l, O[i][7] * inv_l);
        size_t off = (size_t)(qbase + ty * 4 + i) * DIM + h * HD + tx * 8;
        *(float4*)(o + off) = v0;
        *(float4*)(o + off + 4) = v1;
    }
}

// ---------------------------------------------------------------------------
// Launch
// ---------------------------------------------------------------------------
extern "C" void kernel_launch(void* const* d_in, const int* in_sizes, int n_in,
                              void* d_out, int out_size)
{
    (void)in_sizes; (void)n_in; (void)out_size;

    const float* x  = (const float*)d_in[0];
    const float* Wq = (const float*)d_in[1];
    const float* Wk = (const float*)d_in[2];
    const float* Wv = (const float*)d_in[3];
    const float* Wo = (const float*)d_in[4];
    float* out = (float*)d_out;

    float *qp, *kp, *vp, *op;
    cudaGetSymbolAddress((void**)&qp, g_q);
    cudaGetSymbolAddress((void**)&kp, g_k);
    cudaGetSymbolAddress((void**)&vp, g_v);
    cudaGetSymbolAddress((void**)&op, g_o);

    dim3 ggrid(S_LEN / 128, DIM / 64);  // (64, 16)
    gemm_abT<<<ggrid, 256>>>(x, Wq, qp, S_LEN, DIM, DIM);
    gemm_abT<<<ggrid, 256>>>(x, Wk, kp, S_LEN, DIM, DIM);
    gemm_abT<<<ggrid, 256>>>(x, Wv, vp, S_LEN, DIM, DIM);

    int npairs = S_LEN * (DIM / 2);
    rope_kernel<<<(npairs + 255) / 256, 256>>>(qp, kp);

    swa_kernel<<<dim3(S_LEN / 64, NH), 128>>>(qp, kp, vp, op);

    gemm_abT<<<ggrid, 256>>>(op, Wo, out, S_LEN, DIM, DIM);
}

// round 3
// speedup vs baseline: 1.5093x; 1.5093x over previous
#include <cuda_runtime.h>
#include <cuda_bf16.h>
#include <math.h>
#include <stdint.h>

#define S_LEN 8192
#define DIM   1024
#define NH    16
#define HD    64
#define WIN   512

#define KC    3072            // concatenated K = 3 * DIM
#define NKB   96              // KC / 32

// ---------------------------------------------------------------------------
// Scratch (static __device__ allocation is permitted)
// ---------------------------------------------------------------------------
__device__ float g_q[S_LEN * DIM];
__device__ float g_k[S_LEN * DIM];
__device__ float g_v[S_LEN * DIM];
__device__ float g_o[S_LEN * DIM];
__device__ __nv_bfloat16 g_xc[S_LEN * KC];      // [Xh | Xh | Xl]
__device__ __nv_bfloat16 g_oc[S_LEN * KC];      // [Oh | Oh | Ol]
__device__ __nv_bfloat16 g_wc[4 * DIM * KC];    // per W: [Wh | Wl | Wh]

// ---------------------------------------------------------------------------
// fp32 -> bf16 3-segment split.
// mode 0 (activations): segments [hi, hi, lo]
// mode 1 (weights):     segments [hi, lo, hi]
// src rows of 1024 fp32; dst rows of 3072 bf16.
// ---------------------------------------------------------------------------
__global__ void split3_kernel(const float* __restrict__ src,
                              __nv_bfloat16* __restrict__ dst,
                              int nelem, int mode)
{
    int i = (blockIdx.x * blockDim.x + threadIdx.x) * 4;
    if (i >= nelem) return;
    int r = i >> 10;
    int c = i & 1023;
    float4 v = *(const float4*)(src + i);
    float f[4] = {v.x, v.y, v.z, v.w};
    __nv_bfloat16 h[4], l[4];
#pragma unroll
    for (int j = 0; j < 4; j++) {
        h[j] = __float2bfloat16(f[j]);
        l[j] = __float2bfloat16(f[j] - __bfloat162float(h[j]));
    }
    __nv_bfloat16* row = dst + (size_t)r * KC + c;
    // segment 0: hi
    *(__nv_bfloat162*)(row)     = __nv_bfloat162(h[0], h[1]);
    *(__nv_bfloat162*)(row + 2) = __nv_bfloat162(h[2], h[3]);
    if (mode == 0) {
        // [hi, hi, lo]
        *(__nv_bfloat162*)(row + 1024) = __nv_bfloat162(h[0], h[1]);
        *(__nv_bfloat162*)(row + 1026) = __nv_bfloat162(h[2], h[3]);
        *(__nv_bfloat162*)(row + 2048) = __nv_bfloat162(l[0], l[1]);
        *(__nv_bfloat162*)(row + 2050) = __nv_bfloat162(l[2], l[3]);
    } else {
        // [hi, lo, hi]
        *(__nv_bfloat162*)(row + 1024) = __nv_bfloat162(l[0], l[1]);
        *(__nv_bfloat162*)(row + 1026) = __nv_bfloat162(l[2], l[3]);
        *(__nv_bfloat162*)(row + 2048) = __nv_bfloat162(h[0], h[1]);
        *(__nv_bfloat162*)(row + 2050) = __nv_bfloat162(h[2], h[3]);
    }
}

// ---------------------------------------------------------------------------
// bf16 tensor-core GEMM via mma.sync (sm_80 ISA, runs on Blackwell HMMA pipe)
// C[M=8192][N=1024] fp32 = A[M][KC] * B[N][KC]^T, both bf16 K-major.
// CTA 128x128, BK=32, 256 threads, 8 warps (4 M x 2 N), warp tile 32x64.
// cp.async double-buffered smem, ldmatrix fragments.
// ---------------------------------------------------------------------------
#define BM 128
#define BN 128
#define BK 32
#define PAD 8
#define LDS_ROW (BK + PAD)   // 40 bf16 = 80 B row stride (ldmatrix conflict-free)

static __device__ __forceinline__ uint32_t smem_u32(const void* p) {
    return (uint32_t)__cvta_generic_to_shared(p);
}

static __device__ __forceinline__ void cp16(uint32_t dst, const void* src) {
    asm volatile("cp.async.cg.shared.global [%0], [%1], 16;" :: "r"(dst), "l"(src));
}

static __device__ __forceinline__ void ldsm4(uint32_t* r, uint32_t addr) {
    asm volatile("ldmatrix.sync.aligned.m8n8.x4.shared.b16 {%0,%1,%2,%3}, [%4];"
                 : "=r"(r[0]), "=r"(r[1]), "=r"(r[2]), "=r"(r[3]) : "r"(addr));
}

static __device__ __forceinline__ void mma16816(float* c, const uint32_t* a,
                                                uint32_t b0, uint32_t b1) {
    asm volatile(
        "mma.sync.aligned.m16n8k16.row.col.f32.bf16.bf16.f32 "
        "{%0,%1,%2,%3}, {%4,%5,%6,%7}, {%8,%9}, {%0,%1,%2,%3};"
        : "+f"(c[0]), "+f"(c[1]), "+f"(c[2]), "+f"(c[3])
        : "r"(a[0]), "r"(a[1]), "r"(a[2]), "r"(a[3]), "r"(b0), "r"(b1));
}

__global__ __launch_bounds__(256) void gemm_mma(
    const __nv_bfloat16* __restrict__ A,
    const __nv_bfloat16* __restrict__ B,
    float* __restrict__ C)
{
    __shared__ __nv_bfloat16 As[2][BM][LDS_ROW];
    __shared__ __nv_bfloat16 Bs[2][BN][LDS_ROW];

    const int tid = threadIdx.x;
    const int lane = tid & 31;
    const int wid = tid >> 5;
    const int wm = (wid & 3) * 32;     // warp M offset in CTA tile
    const int wn = (wid >> 2) * 64;    // warp N offset
    const int m0 = blockIdx.x * BM;
    const int n0 = blockIdx.y * BN;

    // load slots: 512 16B-chunks per operand tile; thread handles slot tid, tid+256
    const int r0 = tid >> 2, g0 = tid & 3;           // slot tid
    const int r1 = (tid + 256) >> 2, g1 = tid & 3;   // slot tid+256

    auto load_stage = [&](int kb, int buf) {
        const __nv_bfloat16* ap = A + (size_t)(m0 + r0) * KC + kb * BK + g0 * 8;
        cp16(smem_u32(&As[buf][r0][g0 * 8]), ap);
        ap = A + (size_t)(m0 + r1) * KC + kb * BK + g1 * 8;
        cp16(smem_u32(&As[buf][r1][g1 * 8]), ap);
        const __nv_bfloat16* bp = B + (size_t)(n0 + r0) * KC + kb * BK + g0 * 8;
        cp16(smem_u32(&Bs[buf][r0][g0 * 8]), bp);
        bp = B + (size_t)(n0 + r1) * KC + kb * BK + g1 * 8;
        cp16(smem_u32(&Bs[buf][r1][g1 * 8]), bp);
        asm volatile("cp.async.commit_group;");
    };

    float acc[2][8][4];
#pragma unroll
    for (int mi = 0; mi < 2; mi++)
#pragma unroll
        for (int ni = 0; ni < 8; ni++)
#pragma unroll
            for (int q = 0; q < 4; q++) acc[mi][ni][q] = 0.f;

    load_stage(0, 0);

    const int lrow = lane & 15;         // ldmatrix row select
    const int lcol = (lane >> 4) * 8;   // ldmatrix col half

    for (int kb = 0; kb < NKB; kb++) {
        int buf = kb & 1;
        asm volatile("cp.async.wait_group 0;");
        __syncthreads();
        if (kb + 1 < NKB) load_stage(kb + 1, buf ^ 1);

#pragma unroll
        for (int ks = 0; ks < 2; ks++) {
            const int koff = ks * 16;
            uint32_t af[2][4];
#pragma unroll
            for (int mi = 0; mi < 2; mi++)
                ldsm4(af[mi], smem_u32(&As[buf][wm + mi * 16 + lrow][koff + lcol]));
#pragma unroll
            for (int g = 0; g < 4; g++) {
                uint32_t bf[4];
                ldsm4(bf, smem_u32(&Bs[buf][wn + g * 16 + lrow][koff + lcol]));
#pragma unroll
                for (int mi = 0; mi < 2; mi++) {
                    mma16816(acc[mi][g * 2 + 0], af[mi], bf[0], bf[2]);
                    mma16816(acc[mi][g * 2 + 1], af[mi], bf[1], bf[3]);
                }
            }
        }
        __syncthreads();
    }

    // epilogue
    const int erow = lane >> 2;
    const int ecol = (lane & 3) * 2;
#pragma unroll
    for (int mi = 0; mi < 2; mi++) {
#pragma unroll
        for (int ni = 0; ni < 8; ni++) {
            int row = m0 + wm + mi * 16 + erow;
            int col = n0 + wn + ni * 8 + ecol;
            *(float2*)(C + (size_t)row * DIM + col) =
                make_float2(acc[mi][ni][0], acc[mi][ni][1]);
            *(float2*)(C + (size_t)(row + 8) * DIM + col) =
                make_float2(acc[mi][ni][2], acc[mi][ni][3]);
        }
    }
}

// ---------------------------------------------------------------------------
// RoPE (unchanged)
// ---------------------------------------------------------------------------
__global__ void rope_kernel(float* __restrict__ q, float* __restrict__ k)
{
    int idx = blockIdx.x * blockDim.x + threadIdx.x;
    if (idx >= S_LEN * (DIM / 2)) return;
    int s = idx >> 9;
    int p = idx & 511;
    int i = p & 31;
    int h = p >> 5;

    float e = (float)(2 * i) * (1.0f / 64.0f);
    float inv = 1.0f / powf(10000.0f, e);
    float ang = (float)s * inv;
    float sn, cs;
    sincosf(ang, &sn, &cs);

    size_t off = (size_t)s * DIM + (h << 6) + 2 * i;
    float2 qv = *(float2*)(q + off);
    float2 kv = *(float2*)(k + off);
    float2 qo, ko;
    qo.x = qv.x * cs - qv.y * sn;  qo.y = qv.x * sn + qv.y * cs;
    ko.x = kv.x * cs - kv.y * sn;  ko.y = kv.x * sn + kv.y * cs;
    *(float2*)(q + off) = qo;
    *(float2*)(k + off) = ko;
}

// ---------------------------------------------------------------------------
// Sliding-window flash attention (unchanged from R1)
// ---------------------------------------------------------------------------
__global__ __launch_bounds__(128) void swa_kernel(
    const float* __restrict__ q, const float* __restrict__ k,
    const float* __restrict__ v, float* __restrict__ o)
{
    __shared__ float Qt[64][64];
    __shared__ float Kt[64][32];
    __shared__ float Vs[32][64];
    __shared__ float Ps[32][65];

    const int tid = threadIdx.x;
    const int h = blockIdx.y;
    const int qbase = blockIdx.x * 64;
    const int ty = tid >> 3;
    const int tx = tid & 7;

#pragma unroll
    for (int c = 0; c < 8; c++) {
        int f = tid + c * 128;
        int row = f >> 4;
        int dq = (f & 15) << 2;
        float4 vq = *(const float4*)(q + (size_t)(qbase + row) * DIM + h * HD + dq);
        Qt[dq + 0][row] = vq.x;
        Qt[dq + 1][row] = vq.y;
        Qt[dq + 2][row] = vq.z;
        Qt[dq + 3][row] = vq.w;
    }

    float m[4], l[4], O[4][8];
#pragma unroll
    for (int i = 0; i < 4; i++) {
        m[i] = -1e30f;
        l[i] = 0.f;
#pragma unroll
        for (int d = 0; d < 8; d++) O[i][d] = 0.f;
    }

    for (int t = 0; t < 18; t++) {
        int kbase = qbase - 512 + t * 32;
        if (kbase < 0) continue;
        __syncthreads();

#pragma unroll
        for (int c = 0; c < 4; c++) {
            int f = tid + c * 128;
            int j = f >> 4;
            int dq = (f & 15) << 2;
            float4 kv = *(const float4*)(k + (size_t)(kbase + j) * DIM + h * HD + dq);
            Kt[dq + 0][j] = kv.x;
            Kt[dq + 1][j] = kv.y;
            Kt[dq + 2][j] = kv.z;
            Kt[dq + 3][j] = kv.w;
            float4 vv = *(const float4*)(v + (size_t)(kbase + j) * DIM + h * HD + dq);
            *(float4*)&Vs[j][dq] = vv;
        }
        __syncthreads();

        float s_[4][4];
#pragma unroll
        for (int i = 0; i < 4; i++)
#pragma unroll
            for (int j = 0; j < 4; j++) s_[i][j] = 0.f;
#pragma unroll 16
        for (int d = 0; d < 64; d++) {
            float4 a4 = *(const float4*)&Qt[d][ty * 4];
            float4 b4 = *(const float4*)&Kt[d][tx * 4];
            float a[4] = {a4.x, a4.y, a4.z, a4.w};
            float b[4] = {b4.x, b4.y, b4.z, b4.w};
#pragma unroll
            for (int i = 0; i < 4; i++)
#pragma unroll
                for (int j = 0; j < 4; j++)
                    s_[i][j] += a[i] * b[j];
        }

#pragma unroll
        for (int i = 0; i < 4; i++) {
            int qg = qbase + ty * 4 + i;
            float sv[4];
            float rowmax = -1e30f;
#pragma unroll
            for (int j = 0; j < 4; j++) {
                int kg = kbase + tx * 4 + j;
                bool valid = (kg <= qg) && (kg >= qg - (WIN - 1));
                sv[j] = valid ? s_[i][j] * 0.125f : -1e30f;
                rowmax = fmaxf(rowmax, sv[j]);
            }
            rowmax = fmaxf(rowmax, __shfl_xor_sync(0xffffffffu, rowmax, 1));
            rowmax = fmaxf(rowmax, __shfl_xor_sync(0xffffffffu, rowmax, 2));
            rowmax = fmaxf(rowmax, __shfl_xor_sync(0xffffffffu, rowmax, 4));

            float mnew = fmaxf(m[i], rowmax);
            float scale = __expf(m[i] - mnew);
            float rs = 0.f;
#pragma unroll
            for (int j = 0; j < 4; j++) {
                float pj = (sv[j] > -5e29f) ? __expf(sv[j] - mnew) : 0.f;
                Ps[tx * 4 + j][ty * 4 + i] = pj;
                rs += pj;
            }
            rs += __shfl_xor_sync(0xffffffffu, rs, 1);
            rs += __shfl_xor_sync(0xffffffffu, rs, 2);
            rs += __shfl_xor_sync(0xffffffffu, rs, 4);

            l[i] = l[i] * scale + rs;
            m[i] = mnew;
#pragma unroll
            for (int d = 0; d < 8; d++) O[i][d] *= scale;
        }
        __syncthreads();

#pragma unroll 8
        for (int j = 0; j < 32; j++) {
            float a0 = Ps[j][ty * 4 + 0];
            float a1 = Ps[j][ty * 4 + 1];
            float a2 = Ps[j][ty * 4 + 2];
            float a3 = Ps[j][ty * 4 + 3];
            float4 b0 = *(const float4*)&Vs[j][tx * 8];
            float4 b1 = *(const float4*)&Vs[j][tx * 8 + 4];
            float b[8] = {b0.x, b0.y, b0.z, b0.w, b1.x, b1.y, b1.z, b1.w};
#pragma unroll
            for (int d = 0; d < 8; d++) {
                O[0][d] += a0 * b[d];
                O[1][d] += a1 * b[d];
                O[2][d] += a2 * b[d];
                O[3][d] += a3 * b[d];
            }
        }
    }

#pragma unroll
    for (int i = 0; i < 4; i++) {
        float inv_l = 1.0f / l[i];
        float4 v0 = make_float4(O[i][0] * inv_l, O[i][1] * inv_l,
                                O[i][2] * inv_l, O[i][3] * inv_l);
        float4 v1 = make_float4(O[i][4] * inv_l, O[i][5] * inv_l,
                                O[i][6] * inv_l, O[i][7] * inv_l);
        size_t off = (size_t)(qbase + ty * 4 + i) * DIM + h * HD + tx * 8;
        *(float4*)(o + off) = v0;
        *(float4*)(o + off + 4) = v1;
    }
}

// ---------------------------------------------------------------------------
// Launch
// ---------------------------------------------------------------------------
extern "C" void kernel_launch(void* const* d_in, const int* in_sizes, int n_in,
                              void* d_out, int out_size)
{
    (void)in_sizes; (void)n_in; (void)out_size;

    const float* x = (const float*)d_in[0];
    const float* W[4] = {(const float*)d_in[1], (const float*)d_in[2],
                         (const float*)d_in[3], (const float*)d_in[4]};
    float* out = (float*)d_out;

    float *qp, *kp, *vp, *op;
    __nv_bfloat16 *xc, *oc, *wc;
    cudaGetSymbolAddress((void**)&qp, g_q);
    cudaGetSymbolAddress((void**)&kp, g_k);
    cudaGetSymbolAddress((void**)&vp, g_v);
    cudaGetSymbolAddress((void**)&op, g_o);
    cudaGetSymbolAddress((void**)&xc, g_xc);
    cudaGetSymbolAddress((void**)&oc, g_oc);
    cudaGetSymbolAddress((void**)&wc, g_wc);

    const int nx = S_LEN * DIM;
    const int nw = DIM * DIM;

    split3_kernel<<<nx / 4 / 256, 256>>>(x, xc, nx, 0);
    for (int i = 0; i < 4; i++)
        split3_kernel<<<nw / 4 / 256, 256>>>(W[i], wc + (size_t)i * DIM * KC, nw, 1);

    dim3 ggrid(S_LEN / BM, DIM / BN);   // (64, 8)
    gemm_mma<<<ggrid, 256>>>(xc, wc + 0 * (size_t)DIM * KC, qp);
    gemm_mma<<<ggrid, 256>>>(xc, wc + 1 * (size_t)DIM * KC, kp);
    gemm_mma<<<ggrid, 256>>>(xc, wc + 2 * (size_t)DIM * KC, vp);

    int npairs = S_LEN * (DIM / 2);
    rope_kernel<<<(npairs + 255) / 256, 256>>>(qp, kp);

    swa_kernel<<<dim3(S_LEN / 64, NH), 128>>>(qp, kp, vp, op);

    split3_kernel<<<nx / 4 / 256, 256>>>(op, oc, nx, 0);
    gemm_mma<<<ggrid, 256>>>(oc, wc + 3 * (size_t)DIM * KC, out);
}

// round 5
// speedup vs baseline: 1.9332x; 1.2809x over previous
#include <cuda_runtime.h>
#include <cuda_bf16.h>
#include <math.h>
#include <stdint.h>

#define S_LEN 8192
#define DIM   1024
#define NH    16
#define HD    64
#define WIN   512
#define KC    3072            // concatenated K = 3 * DIM
#define NKB   96              // KC / 32

// ---------------------------------------------------------------------------
// Scratch
// ---------------------------------------------------------------------------
__device__ float g_qkv[S_LEN * 3 * DIM];            // fused QKV output fp32
__device__ __nv_bfloat16 g_xc[S_LEN * KC];          // [Xh | Xh | Xl]
__device__ __nv_bfloat16 g_oc[S_LEN * KC];          // [Oh | Oh | Ol] (attention out)
__device__ __nv_bfloat16 g_wc[4 * DIM * KC];        // per W: [Wh | Wl | Wh]
__device__ __nv_bfloat16 g_qc[S_LEN * KC];          // per head: [qh|qh|ql] (rope'd)
__device__ __nv_bfloat16 g_kc[S_LEN * KC];          // per head: [kh|kl|kh] (rope'd)
__device__ __nv_bfloat16 g_vt[NH * 2 * HD * S_LEN]; // [h][dcat(128)][s]: vh rows 0-63, vl 64-127

// ---------------------------------------------------------------------------
// common device helpers
// ---------------------------------------------------------------------------
static __device__ __forceinline__ uint32_t smem_u32(const void* p) {
    return (uint32_t)__cvta_generic_to_shared(p);
}
static __device__ __forceinline__ void cp16(uint32_t dst, const void* src) {
    asm volatile("cp.async.cg.shared.global [%0], [%1], 16;" :: "r"(dst), "l"(src));
}
static __device__ __forceinline__ void ldsm4(uint32_t* r, uint32_t addr) {
    asm volatile("ldmatrix.sync.aligned.m8n8.x4.shared.b16 {%0,%1,%2,%3}, [%4];"
                 : "=r"(r[0]), "=r"(r[1]), "=r"(r[2]), "=r"(r[3]) : "r"(addr));
}
static __device__ __forceinline__ void mma16816(float* c, const uint32_t* a,
                                                uint32_t b0, uint32_t b1) {
    asm volatile(
        "mma.sync.aligned.m16n8k16.row.col.f32.bf16.bf16.f32 "
        "{%0,%1,%2,%3}, {%4,%5,%6,%7}, {%8,%9}, {%0,%1,%2,%3};"
        : "+f"(c[0]), "+f"(c[1]), "+f"(c[2]), "+f"(c[3])
        : "r"(a[0]), "r"(a[1]), "r"(a[2]), "r"(a[3]), "r"(b0), "r"(b1));
}
// split two floats into packed bf16x2 hi and lo parts
static __device__ __forceinline__ void split2(float a, float b,
                                              uint32_t& hi, uint32_t& lo) {
    __nv_bfloat16 ha = __float2bfloat16(a), hb = __float2bfloat16(b);
    __nv_bfloat162 h(ha, hb);
    hi = *(uint32_t*)&h;
    __nv_bfloat162 l(__float2bfloat16(a - __bfloat162float(ha)),
                     __float2bfloat16(b - __bfloat162float(hb)));
    lo = *(uint32_t*)&l;
}

// ---------------------------------------------------------------------------
// fp32 -> bf16 3-segment split.  mode 0: [hi,hi,lo]   mode 1: [hi,lo,hi]
// ---------------------------------------------------------------------------
__global__ void split3_kernel(const float* __restrict__ src,
                              __nv_bfloat16* __restrict__ dst,
                              int nelem, int mode)
{
    int i = (blockIdx.x * blockDim.x + threadIdx.x) * 4;
    if (i >= nelem) return;
    int r = i >> 10;
    int c = i & 1023;
    float4 v = *(const float4*)(src + i);
    float f[4] = {v.x, v.y, v.z, v.w};
    __nv_bfloat16 h[4], l[4];
#pragma unroll
    for (int j = 0; j < 4; j++) {
        h[j] = __float2bfloat16(f[j]);
        l[j] = __float2bfloat16(f[j] - __bfloat162float(h[j]));
    }
    __nv_bfloat16* row = dst + (size_t)r * KC + c;
    *(__nv_bfloat162*)(row)     = __nv_bfloat162(h[0], h[1]);
    *(__nv_bfloat162*)(row + 2) = __nv_bfloat162(h[2], h[3]);
    if (mode == 0) {
        *(__nv_bfloat162*)(row + 1024) = __nv_bfloat162(h[0], h[1]);
        *(__nv_bfloat162*)(row + 1026) = __nv_bfloat162(h[2], h[3]);
        *(__nv_bfloat162*)(row + 2048) = __nv_bfloat162(l[0], l[1]);
        *(__nv_bfloat162*)(row + 2050) = __nv_bfloat162(l[2], l[3]);
    } else {
        *(__nv_bfloat162*)(row + 1024) = __nv_bfloat162(l[0], l[1]);
        *(__nv_bfloat162*)(row + 1026) = __nv_bfloat162(l[2], l[3]);
        *(__nv_bfloat162*)(row + 2048) = __nv_bfloat162(h[0], h[1]);
        *(__nv_bfloat162*)(row + 2050) = __nv_bfloat162(h[2], h[3]);
    }
}

// ---------------------------------------------------------------------------
// bf16 mma GEMM, 3-stage cp.async pipeline.
// C[8192][Nld] fp32 = A[8192][KC] * B[Nld][KC]^T
// CTA 128x128, BK=32, 256 threads, 8 warps (4M x 2N).
// ---------------------------------------------------------------------------
#define BM 128
#define BN 128
#define BK 32
#define LDS_ROW 40          // 32 + 8 pad (80B row)
#define STG_ELEM (BM * LDS_ROW)
#define GEMM_SMEM (3 * 2 * STG_ELEM * 2)   // 61440 bytes

__global__ __launch_bounds__(256) void gemm_mma(
    const __nv_bfloat16* __restrict__ A,
    const __nv_bfloat16* __restrict__ B,
    float* __restrict__ C, int Nld)
{
    extern __shared__ __nv_bfloat16 gsm[];
    __nv_bfloat16* AsB = gsm;                  // 3 stages of BM x LDS_ROW
    __nv_bfloat16* BsB = gsm + 3 * STG_ELEM;

    const int tid = threadIdx.x;
    const int lane = tid & 31;
    const int wid = tid >> 5;
    const int wm = (wid & 3) * 32;
    const int wn = (wid >> 2) * 64;
    const int m0 = blockIdx.x * BM;
    const int n0 = blockIdx.y * BN;

    const int r0 = tid >> 2, g0 = tid & 3;
    const int r1 = (tid + 256) >> 2;

    auto load_stage = [&](int kb, int slot) {
        __nv_bfloat16* As = AsB + slot * STG_ELEM;
        __nv_bfloat16* Bs = BsB + slot * STG_ELEM;
        const __nv_bfloat16* ap = A + (size_t)(m0 + r0) * KC + kb * BK + g0 * 8;
        cp16(smem_u32(&As[r0 * LDS_ROW + g0 * 8]), ap);
        ap = A + (size_t)(m0 + r1) * KC + kb * BK + g0 * 8;
        cp16(smem_u32(&As[r1 * LDS_ROW + g0 * 8]), ap);
        const __nv_bfloat16* bp = B + (size_t)(n0 + r0) * KC + kb * BK + g0 * 8;
        cp16(smem_u32(&Bs[r0 * LDS_ROW + g0 * 8]), bp);
        bp = B + (size_t)(n0 + r1) * KC + kb * BK + g0 * 8;
        cp16(smem_u32(&Bs[r1 * LDS_ROW + g0 * 8]), bp);
        asm volatile("cp.async.commit_group;");
    };

    float acc[2][8][4];
#pragma unroll
    for (int mi = 0; mi < 2; mi++)
#pragma unroll
        for (int ni = 0; ni < 8; ni++)
#pragma unroll
            for (int q = 0; q < 4; q++) acc[mi][ni][q] = 0.f;

    load_stage(0, 0);
    load_stage(1, 1);

    const int lrow = lane & 15;
    const int lcol = (lane >> 4) * 8;

    for (int kb = 0; kb < NKB; kb++) {
        if (kb + 2 < NKB) {
            asm volatile("cp.async.wait_group 1;");
            __syncthreads();
            load_stage(kb + 2, (kb + 2) % 3);
        } else {
            asm volatile("cp.async.wait_group 0;");
            __syncthreads();
        }
        const __nv_bfloat16* As = AsB + (kb % 3) * STG_ELEM;
        const __nv_bfloat16* Bs = BsB + (kb % 3) * STG_ELEM;

#pragma unroll
        for (int ks = 0; ks < 2; ks++) {
            const int koff = ks * 16;
            uint32_t af[2][4];
#pragma unroll
            for (int mi = 0; mi < 2; mi++)
                ldsm4(af[mi], smem_u32(&As[(wm + mi * 16 + lrow) * LDS_ROW + koff + lcol]));
#pragma unroll
            for (int g = 0; g < 4; g++) {
                uint32_t bf[4];
                ldsm4(bf, smem_u32(&Bs[(wn + g * 16 + lrow) * LDS_ROW + koff + lcol]));
#pragma unroll
                for (int mi = 0; mi < 2; mi++) {
                    mma16816(acc[mi][g * 2 + 0], af[mi], bf[0], bf[2]);
                    mma16816(acc[mi][g * 2 + 1], af[mi], bf[1], bf[3]);
                }
            }
        }
    }

    const int erow = lane >> 2;
    const int ecol = (lane & 3) * 2;
#pragma unroll
    for (int mi = 0; mi < 2; mi++)
#pragma unroll
        for (int ni = 0; ni < 8; ni++) {
            int row = m0 + wm + mi * 16 + erow;
            int col = n0 + wn + ni * 8 + ecol;
            *(float2*)(C + (size_t)row * Nld + col) =
                make_float2(acc[mi][ni][0], acc[mi][ni][1]);
            *(float2*)(C + (size_t)(row + 8) * Nld + col) =
                make_float2(acc[mi][ni][2], acc[mi][ni][3]);
        }
}

// ---------------------------------------------------------------------------
// rope_split: reads g_qkv fp32, applies RoPE to q,k, writes:
//   qc [s][h*192+{0,64,128}] = [qh|qh|ql]     kc = [kh|kl|kh]
//   vt [h][dcat][s]: rows 0-63 vh, 64-127 vl  (transposed via smem)
// Block: (64 s-rows, head), 256 threads.
// ---------------------------------------------------------------------------
__global__ __launch_bounds__(256) void rope_split_kernel(
    const float* __restrict__ qkv,
    __nv_bfloat16* __restrict__ qc, __nv_bfloat16* __restrict__ kc,
    __nv_bfloat16* __restrict__ vt)
{
    __shared__ float vsm[64][68];   // stride 68 floats = 272B (16B-aligned rows)

    const int tid = threadIdx.x;
    const int sb = blockIdx.x * 64;
    const int h = blockIdx.y;
    const int r = tid >> 2;          // 0..63 row
    const int pg = tid & 3;          // col group

    // ---- q, k rope + split ----
    {
        int s = sb + r;
        const float* qrow = qkv + (size_t)s * (3 * DIM) + h * HD;
        const float* krow = qrow + DIM;
#pragma unroll
        for (int u = 0; u < 4; u++) {
            int c = pg * 16 + u * 4;          // col within head, 2 pairs
            float4 qv = *(const float4*)(qrow + c);
            float4 kv = *(const float4*)(krow + c);
            float outq[4], outk[4];
#pragma unroll
            for (int pp = 0; pp < 2; pp++) {
                int ip = (c >> 1) + pp;       // pair index 0..31
                float e = (float)(2 * ip) * (1.0f / 64.0f);
                float inv = 1.0f / powf(10000.0f, e);
                float ang = (float)s * inv;
                float sn, cs;
                sincosf(ang, &sn, &cs);
                float qx = pp ? qv.z : qv.x, qy = pp ? qv.w : qv.y;
                float kx = pp ? kv.z : kv.x, ky = pp ? kv.w : kv.y;
                outq[2 * pp + 0] = qx * cs - qy * sn;
                outq[2 * pp + 1] = qx * sn + qy * cs;
                outk[2 * pp + 0] = kx * cs - ky * sn;
                outk[2 * pp + 1] = kx * sn + ky * cs;
            }
            uint32_t qh0, ql0, qh1, ql1, kh0, kl0, kh1, kl1;
            split2(outq[0], outq[1], qh0, ql0);
            split2(outq[2], outq[3], qh1, ql1);
            split2(outk[0], outk[1], kh0, kl0);
            split2(outk[2], outk[3], kh1, kl1);
            __nv_bfloat16* qd = qc + (size_t)s * KC + h * 192 + c;
            __nv_bfloat16* kd = kc + (size_t)s * KC + h * 192 + c;
            *(uint32_t*)(qd)           = qh0; *(uint32_t*)(qd + 2)       = qh1;
            *(uint32_t*)(qd + 64)      = qh0; *(uint32_t*)(qd + 66)      = qh1;
            *(uint32_t*)(qd + 128)     = ql0; *(uint32_t*)(qd + 130)     = ql1;
            *(uint32_t*)(kd)           = kh0; *(uint32_t*)(kd + 2)       = kh1;
            *(uint32_t*)(kd + 64)      = kl0; *(uint32_t*)(kd + 66)      = kl1;
            *(uint32_t*)(kd + 128)     = kh0; *(uint32_t*)(kd + 130)     = kh1;
        }
    }

    // ---- v transpose + split ----
    {
        const float* vrow = qkv + (size_t)(sb + r) * (3 * DIM) + 2 * DIM + h * HD;
#pragma unroll
        for (int u = 0; u < 4; u++) {
            int c = pg * 16 + u * 4;
            *(float4*)&vsm[r][c] = *(const float4*)(vrow + c);
        }
    }
    __syncthreads();
    {
        int dcat = tid >> 1;             // 0..127
        int sh = (tid & 1) * 32;
        int d = dcat & 63;
        bool lo = dcat >= 64;
        uint32_t packs[16];
#pragma unroll
        for (int j = 0; j < 16; j++) {
            float f0 = vsm[sh + 2 * j][d];
            float f1 = vsm[sh + 2 * j + 1][d];
            uint32_t hi, lw;
            split2(f0, f1, hi, lw);
            packs[j] = lo ? lw : hi;
        }
        __nv_bfloat16* dst = vt + ((size_t)(h * 128 + dcat)) * S_LEN + sb + sh;
#pragma unroll
        for (int j = 0; j < 4; j++)
            *(uint4*)(dst + j * 8) = make_uint4(packs[4 * j], packs[4 * j + 1],
                                                packs[4 * j + 2], packs[4 * j + 3]);
    }
}

// ---------------------------------------------------------------------------
// Tensor-core sliding-window flash attention.
// CTA: (64 q-rows, head), 128 threads (4 warps, 16 q-rows each).
// Key tiles of 64; S via K=192 concat; PV via register P (3 split terms).
// Writes oc = [Oh|Oh|Ol] concat directly.
// ---------------------------------------------------------------------------
#define QLD 200      // 192 + 8 pad
#define VLD 72       // 64 + 8 pad
#define SWA_SMEM (64 * QLD * 2 + 64 * QLD * 2 + 128 * VLD * 2)  // 69632

__global__ __launch_bounds__(128) void swa_mma_kernel(
    const __nv_bfloat16* __restrict__ qc, const __nv_bfloat16* __restrict__ kc,
    const __nv_bfloat16* __restrict__ vt, __nv_bfloat16* __restrict__ oc)
{
    extern __shared__ char smem[];
    __nv_bfloat16* Qs = (__nv_bfloat16*)smem;                    // [64][QLD]
    __nv_bfloat16* Ks = (__nv_bfloat16*)(smem + 64 * QLD * 2);   // [64][QLD]
    __nv_bfloat16* Vc = (__nv_bfloat16*)(smem + 2 * 64 * QLD * 2); // [128][VLD]

    const int tid = threadIdx.x;
    const int lane = tid & 31;
    const int w = tid >> 5;
    const int qbase = blockIdx.x * 64;
    const int h = blockIdx.y;
    const int lrow = lane & 15;
    const int lcol = (lane >> 4) * 8;

    // load Q tile (64 x 192) via cp.async
    {
#pragma unroll
        for (int i = 0; i < 12; i++) {
            int c = tid + i * 128;          // 1536 16B chunks
            int row = c / 24, off = (c % 24) * 8;
            cp16(smem_u32(&Qs[row * QLD + off]),
                 qc + (size_t)(qbase + row) * KC + h * 192 + off);
        }
        asm volatile("cp.async.commit_group;");
    }

    float oacc[8][4];
#pragma unroll
    for (int b = 0; b < 8; b++)
#pragma unroll
        for (int q = 0; q < 4; q++) oacc[b][q] = 0.f;
    float mrun0 = -1e30f, mrun1 = -1e30f, lrun0 = 0.f, lrun1 = 0.f;

    const int qg0 = qbase + w * 16 + (lane >> 2);
    const int qg1 = qg0 + 8;

    for (int t = 0; t < 9; t++) {
        int kbase = qbase - 512 + t * 64;
        if (kbase < 0) continue;
        __syncthreads();   // previous tile consumed

        // load K tile (64 x 192) and V tile (128 x 64)
#pragma unroll
        for (int i = 0; i < 12; i++) {
            int c = tid + i * 128;
            int row = c / 24, off = (c % 24) * 8;
            cp16(smem_u32(&Ks[row * QLD + off]),
                 kc + (size_t)(kbase + row) * KC + h * 192 + off);
        }
#pragma unroll
        for (int i = 0; i < 8; i++) {
            int c = tid + i * 128;          // 1024 chunks
            int dcat = c >> 3, j0 = (c & 7) * 8;
            cp16(smem_u32(&Vc[dcat * VLD + j0]),
                 vt + ((size_t)(h * 128 + dcat)) * S_LEN + kbase + j0);
        }
        asm volatile("cp.async.commit_group;");
        asm volatile("cp.async.wait_group 0;");
        __syncthreads();

        // ---- S = Q K^T (K=192) ----
        float sacc[8][4];
#pragma unroll
        for (int b = 0; b < 8; b++)
#pragma unroll
            for (int q = 0; q < 4; q++) sacc[b][q] = 0.f;
#pragma unroll
        for (int ks = 0; ks < 12; ks++) {
            uint32_t af[4];
            ldsm4(af, smem_u32(&Qs[(w * 16 + lrow) * QLD + ks * 16 + lcol]));
#pragma unroll
            for (int g = 0; g < 4; g++) {
                uint32_t bf[4];
                ldsm4(bf, smem_u32(&Ks[(g * 16 + lrow) * QLD + ks * 16 + lcol]));
                mma16816(sacc[g * 2 + 0], af, bf[0], bf[2]);
                mma16816(sacc[g * 2 + 1], af, bf[1], bf[3]);
            }
        }

        // ---- mask + scale ----
#pragma unroll
        for (int b = 0; b < 8; b++) {
            int j0 = kbase + b * 8 + (lane & 3) * 2;
#pragma unroll
            for (int q = 0; q < 4; q++) {
                int kg = j0 + (q & 1);
                int qg = (q < 2) ? qg0 : qg1;
                bool valid = (kg <= qg) && (kg + (WIN - 1) >= qg);
                sacc[b][q] = valid ? sacc[b][q] * 0.125f : -1e30f;
            }
        }

        // ---- online softmax ----
        float rm0 = -1e30f, rm1 = -1e30f;
#pragma unroll
        for (int b = 0; b < 8; b++) {
            rm0 = fmaxf(rm0, fmaxf(sacc[b][0], sacc[b][1]));
            rm1 = fmaxf(rm1, fmaxf(sacc[b][2], sacc[b][3]));
        }
        rm0 = fmaxf(rm0, __shfl_xor_sync(0xffffffffu, rm0, 1));
        rm0 = fmaxf(rm0, __shfl_xor_sync(0xffffffffu, rm0, 2));
        rm1 = fmaxf(rm1, __shfl_xor_sync(0xffffffffu, rm1, 1));
        rm1 = fmaxf(rm1, __shfl_xor_sync(0xffffffffu, rm1, 2));

        float mn0 = fmaxf(mrun0, rm0), mn1 = fmaxf(mrun1, rm1);
        float sc0 = __expf(mrun0 - mn0), sc1 = __expf(mrun1 - mn1);
        float rs0 = 0.f, rs1 = 0.f;
#pragma unroll
        for (int b = 0; b < 8; b++) {
            float p0 = (sacc[b][0] > -5e29f) ? __expf(sacc[b][0] - mn0) : 0.f;
            float p1 = (sacc[b][1] > -5e29f) ? __expf(sacc[b][1] - mn0) : 0.f;
            float p2 = (sacc[b][2] > -5e29f) ? __expf(sacc[b][2] - mn1) : 0.f;
            float p3 = (sacc[b][3] > -5e29f) ? __expf(sacc[b][3] - mn1) : 0.f;
            sacc[b][0] = p0; sacc[b][1] = p1; sacc[b][2] = p2; sacc[b][3] = p3;
            rs0 += p0 + p1;
            rs1 += p2 + p3;
        }
        rs0 += __shfl_xor_sync(0xffffffffu, rs0, 1);
        rs0 += __shfl_xor_sync(0xffffffffu, rs0, 2);
        rs1 += __shfl_xor_sync(0xffffffffu, rs1, 1);
        rs1 += __shfl_xor_sync(0xffffffffu, rs1, 2);
        lrun0 = lrun0 * sc0 + rs0;
        lrun1 = lrun1 * sc1 + rs1;
        mrun0 = mn0;
        mrun1 = mn1;
#pragma unroll
        for (int b = 0; b < 8; b++) {
            oacc[b][0] *= sc0; oacc[b][1] *= sc0;
            oacc[b][2] *= sc1; oacc[b][3] *= sc1;
        }

        // ---- O += P V  (terms: Ph*Vh, Pl*Vh, Ph*Vl) ----
#pragma unroll
        for (int ks = 0; ks < 4; ks++) {
            uint32_t aH[4], aL[4];
            split2(sacc[2 * ks][0],     sacc[2 * ks][1],     aH[0], aL[0]);
            split2(sacc[2 * ks][2],     sacc[2 * ks][3],     aH[1], aL[1]);
            split2(sacc[2 * ks + 1][0], sacc[2 * ks + 1][1], aH[2], aL[2]);
            split2(sacc[2 * ks + 1][2], sacc[2 * ks + 1][3], aH[3], aL[3]);
#pragma unroll
            for (int db = 0; db < 4; db++) {
                uint32_t bh[4], bl[4];
                ldsm4(bh, smem_u32(&Vc[(db * 16 + lrow) * VLD + ks * 16 + lcol]));
                ldsm4(bl, smem_u32(&Vc[((64 + db * 16) + lrow) * VLD + ks * 16 + lcol]));
                mma16816(oacc[2 * db + 0], aH, bh[0], bh[2]);
                mma16816(oacc[2 * db + 1], aH, bh[1], bh[3]);
                mma16816(oacc[2 * db + 0], aL, bh[0], bh[2]);
                mma16816(oacc[2 * db + 1], aL, bh[1], bh[3]);
                mma16816(oacc[2 * db + 0], aH, bl[0], bl[2]);
                mma16816(oacc[2 * db + 1], aH, bl[1], bl[3]);
            }
        }
    }

    // ---- normalize + write oc concat ----
    float inv0 = 1.0f / lrun0, inv1 = 1.0f / lrun1;
#pragma unroll
    for (int b = 0; b < 8; b++) {
        int d = b * 8 + (lane & 3) * 2;
        uint32_t hi0, lo0, hi1, lo1;
        split2(oacc[b][0] * inv0, oacc[b][1] * inv0, hi0, lo0);
        split2(oacc[b][2] * inv1, oacc[b][3] * inv1, hi1, lo1);
        __nv_bfloat16* d0 = oc + (size_t)qg0 * KC + h * HD + d;
        __nv_bfloat16* d1 = oc + (size_t)qg1 * KC + h * HD + d;
        *(uint32_t*)(d0)        = hi0;
        *(uint32_t*)(d0 + 1024) = hi0;
        *(uint32_t*)(d0 + 2048) = lo0;
        *(uint32_t*)(d1)        = hi1;
        *(uint32_t*)(d1 + 1024) = hi1;
        *(uint32_t*)(d1 + 2048) = lo1;
    }
}

// ---------------------------------------------------------------------------
// Launch
// ---------------------------------------------------------------------------
extern "C" void kernel_launch(void* const* d_in, const int* in_sizes, int n_in,
                              void* d_out, int out_size)
{
    (void)in_sizes; (void)n_in; (void)out_size;

    const float* x = (const float*)d_in[0];
    const float* W[4] = {(const float*)d_in[1], (const float*)d_in[2],
                         (const float*)d_in[3], (const float*)d_in[4]};
    float* out = (float*)d_out;

    float* qkv;
    __nv_bfloat16 *xc, *oc, *wc, *qc, *kc, *vt;
    cudaGetSymbolAddress((void**)&qkv, g_qkv);
    cudaGetSymbolAddress((void**)&xc, g_xc);
    cudaGetSymbolAddress((void**)&oc, g_oc);
    cudaGetSymbolAddress((void**)&wc, g_wc);
    cudaGetSymbolAddress((void**)&qc, g_qc);
    cudaGetSymbolAddress((void**)&kc, g_kc);
    cudaGetSymbolAddress((void**)&vt, g_vt);

    cudaFuncSetAttribute(gemm_mma, cudaFuncAttributeMaxDynamicSharedMemorySize, GEMM_SMEM);
    cudaFuncSetAttribute(swa_mma_kernel, cudaFuncAttributeMaxDynamicSharedMemorySize, SWA_SMEM);

    const int nx = S_LEN * DIM;
    const int nw = DIM * DIM;

    split3_kernel<<<nx / 4 / 256, 256>>>(x, xc, nx, 0);
    for (int i = 0; i < 4; i++)
        split3_kernel<<<nw / 4 / 256, 256>>>(W[i], wc + (size_t)i * DIM * KC, nw, 1);

    // fused QKV projection: N = 3072
    gemm_mma<<<dim3(S_LEN / BM, 3 * DIM / BN), 256, GEMM_SMEM>>>(xc, wc, qkv, 3 * DIM);

    rope_split_kernel<<<dim3(S_LEN / 64, NH), 256>>>(qkv, qc, kc, vt);

    swa_mma_kernel<<<dim3(S_LEN / 64, NH), 128, SWA_SMEM>>>(qc, kc, vt, oc);

    // output projection: N = 1024
    gemm_mma<<<dim3(S_LEN / BM, DIM / BN), 256, GEMM_SMEM>>>(
        oc, wc + (size_t)3 * DIM * KC, out, DIM);
}

// round 6
// speedup vs baseline: 2.0166x; 1.0432x over previous
#include <cuda_runtime.h>
#include <cuda_bf16.h>
#include <math.h>
#include <stdint.h>

#define S_LEN 8192
#define DIM   1024
#define NH    16
#define HD    64
#define WIN   512
#define KC    3072            // concatenated K = 3 * DIM
#define NKB   96              // KC / 32

// ---------------------------------------------------------------------------
// Scratch
// ---------------------------------------------------------------------------
__device__ float g_qkv[S_LEN * 3 * DIM];            // fused QKV output fp32
__device__ __nv_bfloat16 g_xc[S_LEN * KC];          // [Xh | Xh | Xl]
__device__ __nv_bfloat16 g_oc[S_LEN * KC];          // [Oh | Oh | Ol] (attention out)
__device__ __nv_bfloat16 g_wc[4 * DIM * KC];        // per W: [Wh | Wl | Wh]
__device__ __nv_bfloat16 g_qc[S_LEN * KC];          // per head: [qh|qh|ql] (rope'd)
__device__ __nv_bfloat16 g_kc[S_LEN * KC];          // per head: [kh|kl|kh] (rope'd)
__device__ __nv_bfloat16 g_vt[NH * 2 * HD * S_LEN]; // [h][dcat(128)][s]: vh rows 0-63, vl 64-127

// ---------------------------------------------------------------------------
// common device helpers
// ---------------------------------------------------------------------------
static __device__ __forceinline__ uint32_t smem_u32(const void* p) {
    return (uint32_t)__cvta_generic_to_shared(p);
}
static __device__ __forceinline__ void cp16(uint32_t dst, const void* src) {
    asm volatile("cp.async.cg.shared.global [%0], [%1], 16;" :: "r"(dst), "l"(src));
}
static __device__ __forceinline__ void ldsm4(uint32_t* r, uint32_t addr) {
    asm volatile("ldmatrix.sync.aligned.m8n8.x4.shared.b16 {%0,%1,%2,%3}, [%4];"
                 : "=r"(r[0]), "=r"(r[1]), "=r"(r[2]), "=r"(r[3]) : "r"(addr));
}
static __device__ __forceinline__ void mma16816(float* c, const uint32_t* a,
                                                uint32_t b0, uint32_t b1) {
    asm volatile(
        "mma.sync.aligned.m16n8k16.row.col.f32.bf16.bf16.f32 "
        "{%0,%1,%2,%3}, {%4,%5,%6,%7}, {%8,%9}, {%0,%1,%2,%3};"
        : "+f"(c[0]), "+f"(c[1]), "+f"(c[2]), "+f"(c[3])
        : "r"(a[0]), "r"(a[1]), "r"(a[2]), "r"(a[3]), "r"(b0), "r"(b1));
}
// split two floats into packed bf16x2 hi and lo parts
static __device__ __forceinline__ void split2(float a, float b,
                                              uint32_t& hi, uint32_t& lo) {
    __nv_bfloat16 ha = __float2bfloat16(a), hb = __float2bfloat16(b);
    __nv_bfloat162 h(ha, hb);
    hi = *(uint32_t*)&h;
    __nv_bfloat162 l(__float2bfloat16(a - __bfloat162float(ha)),
                     __float2bfloat16(b - __bfloat162float(hb)));
    lo = *(uint32_t*)&l;
}

// ---------------------------------------------------------------------------
// fp32 -> bf16 3-segment split (activations): [hi, hi, lo]
// ---------------------------------------------------------------------------
__global__ void split3_kernel(const float* __restrict__ src,
                              __nv_bfloat16* __restrict__ dst, int nelem)
{
    int i = (blockIdx.x * blockDim.x + threadIdx.x) * 4;
    if (i >= nelem) return;
    int r = i >> 10;
    int c = i & 1023;
    float4 v = *(const float4*)(src + i);
    float f[4] = {v.x, v.y, v.z, v.w};
    __nv_bfloat16 h[4], l[4];
#pragma unroll
    for (int j = 0; j < 4; j++) {
        h[j] = __float2bfloat16(f[j]);
        l[j] = __float2bfloat16(f[j] - __bfloat162float(h[j]));
    }
    __nv_bfloat16* row = dst + (size_t)r * KC + c;
    *(__nv_bfloat162*)(row)        = __nv_bfloat162(h[0], h[1]);
    *(__nv_bfloat162*)(row + 2)    = __nv_bfloat162(h[2], h[3]);
    *(__nv_bfloat162*)(row + 1024) = __nv_bfloat162(h[0], h[1]);
    *(__nv_bfloat162*)(row + 1026) = __nv_bfloat162(h[2], h[3]);
    *(__nv_bfloat162*)(row + 2048) = __nv_bfloat162(l[0], l[1]);
    *(__nv_bfloat162*)(row + 2050) = __nv_bfloat162(l[2], l[3]);
}

// weights: [hi, lo, hi]; all four weights in one launch (blockIdx.y selects)
__global__ void split3_w_kernel(const float* __restrict__ W0,
                                const float* __restrict__ W1,
                                const float* __restrict__ W2,
                                const float* __restrict__ W3,
                                __nv_bfloat16* __restrict__ dstbase)
{
    const float* srcs[4] = {W0, W1, W2, W3};
    const float* src = srcs[blockIdx.y];
    __nv_bfloat16* dst = dstbase + (size_t)blockIdx.y * DIM * KC;

    int i = (blockIdx.x * blockDim.x + threadIdx.x) * 4;
    if (i >= DIM * DIM) return;
    int r = i >> 10;
    int c = i & 1023;
    float4 v = *(const float4*)(src + i);
    float f[4] = {v.x, v.y, v.z, v.w};
    __nv_bfloat16 h[4], l[4];
#pragma unroll
    for (int j = 0; j < 4; j++) {
        h[j] = __float2bfloat16(f[j]);
        l[j] = __float2bfloat16(f[j] - __bfloat162float(h[j]));
    }
    __nv_bfloat16* row = dst + (size_t)r * KC + c;
    *(__nv_bfloat162*)(row)        = __nv_bfloat162(h[0], h[1]);
    *(__nv_bfloat162*)(row + 2)    = __nv_bfloat162(h[2], h[3]);
    *(__nv_bfloat162*)(row + 1024) = __nv_bfloat162(l[0], l[1]);
    *(__nv_bfloat162*)(row + 1026) = __nv_bfloat162(l[2], l[3]);
    *(__nv_bfloat162*)(row + 2048) = __nv_bfloat162(h[0], h[1]);
    *(__nv_bfloat162*)(row + 2050) = __nv_bfloat162(h[2], h[3]);
}

// ---------------------------------------------------------------------------
// bf16 mma GEMM, 3-stage cp.async pipeline.
// C[8192][Nld] fp32 = A[8192][KC] * B[Nld][KC]^T
// CTA 128x128, BK=32, 128 threads, 4 warps (2M x 2N), warp tile 64x64.
// ---------------------------------------------------------------------------
#define BM 128
#define BN 128
#define BK 32
#define LDS_ROW 40          // 32 + 8 pad (80B row)
#define STG_ELEM (BM * LDS_ROW)
#define GEMM_SMEM (3 * 2 * STG_ELEM * 2)   // 61440 bytes

__global__ __launch_bounds__(128) void gemm_mma(
    const __nv_bfloat16* __restrict__ A,
    const __nv_bfloat16* __restrict__ B,
    float* __restrict__ C, int Nld)
{
    extern __shared__ __nv_bfloat16 gsm[];
    __nv_bfloat16* AsB = gsm;                  // 3 stages of BM x LDS_ROW
    __nv_bfloat16* BsB = gsm + 3 * STG_ELEM;

    const int tid = threadIdx.x;
    const int lane = tid & 31;
    const int wid = tid >> 5;
    const int wm = (wid & 1) * 64;     // warp M offset
    const int wn = (wid >> 1) * 64;    // warp N offset
    const int m0 = blockIdx.x * BM;
    const int n0 = blockIdx.y * BN;

    // loads: 512 16B-chunks per operand; thread handles chunks tid + j*128
    const int r0 = tid >> 2, g0 = (tid & 3) * 8;

    auto load_stage = [&](int kb, int slot) {
        __nv_bfloat16* As = AsB + slot * STG_ELEM;
        __nv_bfloat16* Bs = BsB + slot * STG_ELEM;
#pragma unroll
        for (int j = 0; j < 4; j++) {
            int row = r0 + j * 32;
            cp16(smem_u32(&As[row * LDS_ROW + g0]),
                 A + (size_t)(m0 + row) * KC + kb * BK + g0);
            cp16(smem_u32(&Bs[row * LDS_ROW + g0]),
                 B + (size_t)(n0 + row) * KC + kb * BK + g0);
        }
        asm volatile("cp.async.commit_group;");
    };

    float acc[4][8][4];
#pragma unroll
    for (int mi = 0; mi < 4; mi++)
#pragma unroll
        for (int ni = 0; ni < 8; ni++)
#pragma unroll
            for (int q = 0; q < 4; q++) acc[mi][ni][q] = 0.f;

    load_stage(0, 0);
    load_stage(1, 1);

    const int lrow = lane & 15;
    const int lcol = (lane >> 4) * 8;

    for (int kb = 0; kb < NKB; kb++) {
        if (kb + 2 < NKB) {
            asm volatile("cp.async.wait_group 1;");
            __syncthreads();
            load_stage(kb + 2, (kb + 2) % 3);
        } else {
            asm volatile("cp.async.wait_group 0;");
            __syncthreads();
        }
        const __nv_bfloat16* As = AsB + (kb % 3) * STG_ELEM;
        const __nv_bfloat16* Bs = BsB + (kb % 3) * STG_ELEM;

#pragma unroll
        for (int ks = 0; ks < 2; ks++) {
            const int koff = ks * 16;
            uint32_t af[4][4], bfr[4][4];
#pragma unroll
            for (int mi = 0; mi < 4; mi++)
                ldsm4(af[mi], smem_u32(&As[(wm + mi * 16 + lrow) * LDS_ROW + koff + lcol]));
#pragma unroll
            for (int g = 0; g < 4; g++)
                ldsm4(bfr[g], smem_u32(&Bs[(wn + g * 16 + lrow) * LDS_ROW + koff + lcol]));
#pragma unroll
            for (int g = 0; g < 4; g++)
#pragma unroll
                for (int mi = 0; mi < 4; mi++) {
                    mma16816(acc[mi][g * 2 + 0], af[mi], bfr[g][0], bfr[g][2]);
                    mma16816(acc[mi][g * 2 + 1], af[mi], bfr[g][1], bfr[g][3]);
                }
        }
        __syncthreads();
    }

    const int erow = lane >> 2;
    const int ecol = (lane & 3) * 2;
#pragma unroll
    for (int mi = 0; mi < 4; mi++)
#pragma unroll
        for (int ni = 0; ni < 8; ni++) {
            int row = m0 + wm + mi * 16 + erow;
            int col = n0 + wn + ni * 8 + ecol;
            *(float2*)(C + (size_t)row * Nld + col) =
                make_float2(acc[mi][ni][0], acc[mi][ni][1]);
            *(float2*)(C + (size_t)(row + 8) * Nld + col) =
                make_float2(acc[mi][ni][2], acc[mi][ni][3]);
        }
}

// ---------------------------------------------------------------------------
// rope_split (unchanged from R5)
// ---------------------------------------------------------------------------
__global__ __launch_bounds__(256) void rope_split_kernel(
    const float* __restrict__ qkv,
    __nv_bfloat16* __restrict__ qc, __nv_bfloat16* __restrict__ kc,
    __nv_bfloat16* __restrict__ vt)
{
    __shared__ float vsm[64][68];   // stride 68 floats = 272B (16B-aligned rows)

    const int tid = threadIdx.x;
    const int sb = blockIdx.x * 64;
    const int h = blockIdx.y;
    const int r = tid >> 2;
    const int pg = tid & 3;

    {
        int s = sb + r;
        const float* qrow = qkv + (size_t)s * (3 * DIM) + h * HD;
        const float* krow = qrow + DIM;
#pragma unroll
        for (int u = 0; u < 4; u++) {
            int c = pg * 16 + u * 4;
            float4 qv = *(const float4*)(qrow + c);
            float4 kv = *(const float4*)(krow + c);
            float outq[4], outk[4];
#pragma unroll
            for (int pp = 0; pp < 2; pp++) {
                int ip = (c >> 1) + pp;
                float e = (float)(2 * ip) * (1.0f / 64.0f);
                float inv = 1.0f / powf(10000.0f, e);
                float ang = (float)s * inv;
                float sn, cs;
                sincosf(ang, &sn, &cs);
                float qx = pp ? qv.z : qv.x, qy = pp ? qv.w : qv.y;
                float kx = pp ? kv.z : kv.x, ky = pp ? kv.w : kv.y;
                outq[2 * pp + 0] = qx * cs - qy * sn;
                outq[2 * pp + 1] = qx * sn + qy * cs;
                outk[2 * pp + 0] = kx * cs - ky * sn;
                outk[2 * pp + 1] = kx * sn + ky * cs;
            }
            uint32_t qh0, ql0, qh1, ql1, kh0, kl0, kh1, kl1;
            split2(outq[0], outq[1], qh0, ql0);
            split2(outq[2], outq[3], qh1, ql1);
            split2(outk[0], outk[1], kh0, kl0);
            split2(outk[2], outk[3], kh1, kl1);
            __nv_bfloat16* qd = qc + (size_t)s * KC + h * 192 + c;
            __nv_bfloat16* kd = kc + (size_t)s * KC + h * 192 + c;
            *(uint32_t*)(qd)           = qh0; *(uint32_t*)(qd + 2)       = qh1;
            *(uint32_t*)(qd + 64)      = qh0; *(uint32_t*)(qd + 66)      = qh1;
            *(uint32_t*)(qd + 128)     = ql0; *(uint32_t*)(qd + 130)     = ql1;
            *(uint32_t*)(kd)           = kh0; *(uint32_t*)(kd + 2)       = kh1;
            *(uint32_t*)(kd + 64)      = kl0; *(uint32_t*)(kd + 66)      = kl1;
            *(uint32_t*)(kd + 128)     = kh0; *(uint32_t*)(kd + 130)     = kh1;
        }
    }

    {
        const float* vrow = qkv + (size_t)(sb + r) * (3 * DIM) + 2 * DIM + h * HD;
#pragma unroll
        for (int u = 0; u < 4; u++) {
            int c = pg * 16 + u * 4;
            *(float4*)&vsm[r][c] = *(const float4*)(vrow + c);
        }
    }
    __syncthreads();
    {
        int dcat = tid >> 1;
        int sh = (tid & 1) * 32;
        int d = dcat & 63;
        bool lo = dcat >= 64;
        uint32_t packs[16];
#pragma unroll
        for (int j = 0; j < 16; j++) {
            float f0 = vsm[sh + 2 * j][d];
            float f1 = vsm[sh + 2 * j + 1][d];
            uint32_t hi, lw;
            split2(f0, f1, hi, lw);
            packs[j] = lo ? lw : hi;
        }
        __nv_bfloat16* dst = vt + ((size_t)(h * 128 + dcat)) * S_LEN + sb + sh;
#pragma unroll
        for (int j = 0; j < 4; j++)
            *(uint4*)(dst + j * 8) = make_uint4(packs[4 * j], packs[4 * j + 1],
                                                packs[4 * j + 2], packs[4 * j + 3]);
    }
}

// ---------------------------------------------------------------------------
// Tensor-core sliding-window flash attention (unchanged from R5)
// ---------------------------------------------------------------------------
#define QLD 200      // 192 + 8 pad
#define VLD 72       // 64 + 8 pad
#define SWA_SMEM (64 * QLD * 2 + 64 * QLD * 2 + 128 * VLD * 2)  // 69632

__global__ __launch_bounds__(128) void swa_mma_kernel(
    const __nv_bfloat16* __restrict__ qc, const __nv_bfloat16* __restrict__ kc,
    const __nv_bfloat16* __restrict__ vt, __nv_bfloat16* __restrict__ oc)
{
    extern __shared__ char smem[];
    __nv_bfloat16* Qs = (__nv_bfloat16*)smem;                    // [64][QLD]
    __nv_bfloat16* Ks = (__nv_bfloat16*)(smem + 64 * QLD * 2);   // [64][QLD]
    __nv_bfloat16* Vc = (__nv_bfloat16*)(smem + 2 * 64 * QLD * 2); // [128][VLD]

    const int tid = threadIdx.x;
    const int lane = tid & 31;
    const int w = tid >> 5;
    const int qbase = blockIdx.x * 64;
    const int h = blockIdx.y;
    const int lrow = lane & 15;
    const int lcol = (lane >> 4) * 8;

    {
#pragma unroll
        for (int i = 0; i < 12; i++) {
            int c = tid + i * 128;
            int row = c / 24, off = (c % 24) * 8;
            cp16(smem_u32(&Qs[row * QLD + off]),
                 qc + (size_t)(qbase + row) * KC + h * 192 + off);
        }
        asm volatile("cp.async.commit_group;");
    }

    float oacc[8][4];
#pragma unroll
    for (int b = 0; b < 8; b++)
#pragma unroll
        for (int q = 0; q < 4; q++) oacc[b][q] = 0.f;
    float mrun0 = -1e30f, mrun1 = -1e30f, lrun0 = 0.f, lrun1 = 0.f;

    const int qg0 = qbase + w * 16 + (lane >> 2);
    const int qg1 = qg0 + 8;

    for (int t = 0; t < 9; t++) {
        int kbase = qbase - 512 + t * 64;
        if (kbase < 0) continue;
        __syncthreads();

#pragma unroll
        for (int i = 0; i < 12; i++) {
            int c = tid + i * 128;
            int row = c / 24, off = (c % 24) * 8;
            cp16(smem_u32(&Ks[row * QLD + off]),
                 kc + (size_t)(kbase + row) * KC + h * 192 + off);
        }
#pragma unroll
        for (int i = 0; i < 8; i++) {
            int c = tid + i * 128;
            int dcat = c >> 3, j0 = (c & 7) * 8;
            cp16(smem_u32(&Vc[dcat * VLD + j0]),
                 vt + ((size_t)(h * 128 + dcat)) * S_LEN + kbase + j0);
        }
        asm volatile("cp.async.commit_group;");
        asm volatile("cp.async.wait_group 0;");
        __syncthreads();

        float sacc[8][4];
#pragma unroll
        for (int b = 0; b < 8; b++)
#pragma unroll
            for (int q = 0; q < 4; q++) sacc[b][q] = 0.f;
#pragma unroll
        for (int ks = 0; ks < 12; ks++) {
            uint32_t af[4];
            ldsm4(af, smem_u32(&Qs[(w * 16 + lrow) * QLD + ks * 16 + lcol]));
#pragma unroll
            for (int g = 0; g < 4; g++) {
                uint32_t bf[4];
                ldsm4(bf, smem_u32(&Ks[(g * 16 + lrow) * QLD + ks * 16 + lcol]));
                mma16816(sacc[g * 2 + 0], af, bf[0], bf[2]);
                mma16816(sacc[g * 2 + 1], af, bf[1], bf[3]);
            }
        }

#pragma unroll
        for (int b = 0; b < 8; b++) {
            int j0 = kbase + b * 8 + (lane & 3) * 2;
#pragma unroll
            for (int q = 0; q < 4; q++) {
                int kg = j0 + (q & 1);
                int qg = (q < 2) ? qg0 : qg1;
                bool valid = (kg <= qg) && (kg + (WIN - 1) >= qg);
                sacc[b][q] = valid ? sacc[b][q] * 0.125f : -1e30f;
            }
        }

        float rm0 = -1e30f, rm1 = -1e30f;
#pragma unroll
        for (int b = 0; b < 8; b++) {
            rm0 = fmaxf(rm0, fmaxf(sacc[b][0], sacc[b][1]));
            rm1 = fmaxf(rm1, fmaxf(sacc[b][2], sacc[b][3]));
        }
        rm0 = fmaxf(rm0, __shfl_xor_sync(0xffffffffu, rm0, 1));
        rm0 = fmaxf(rm0, __shfl_xor_sync(0xffffffffu, rm0, 2));
        rm1 = fmaxf(rm1, __shfl_xor_sync(0xffffffffu, rm1, 1));
        rm1 = fmaxf(rm1, __shfl_xor_sync(0xffffffffu, rm1, 2));

        float mn0 = fmaxf(mrun0, rm0), mn1 = fmaxf(mrun1, rm1);
        float sc0 = __expf(mrun0 - mn0), sc1 = __expf(mrun1 - mn1);
        float rs0 = 0.f, rs1 = 0.f;
#pragma unroll
        for (int b = 0; b < 8; b++) {
            float p0 = (sacc[b][0] > -5e29f) ? __expf(sacc[b][0] - mn0) : 0.f;
            float p1 = (sacc[b][1] > -5e29f) ? __expf(sacc[b][1] - mn0) : 0.f;
            float p2 = (sacc[b][2] > -5e29f) ? __expf(sacc[b][2] - mn1) : 0.f;
            float p3 = (sacc[b][3] > -5e29f) ? __expf(sacc[b][3] - mn1) : 0.f;
            sacc[b][0] = p0; sacc[b][1] = p1; sacc[b][2] = p2; sacc[b][3] = p3;
            rs0 += p0 + p1;
            rs1 += p2 + p3;
        }
        rs0 += __shfl_xor_sync(0xffffffffu, rs0, 1);
        rs0 += __shfl_xor_sync(0xffffffffu, rs0, 2);
        rs1 += __shfl_xor_sync(0xffffffffu, rs1, 1);
        rs1 += __shfl_xor_sync(0xffffffffu, rs1, 2);
        lrun0 = lrun0 * sc0 + rs0;
        lrun1 = lrun1 * sc1 + rs1;
        mrun0 = mn0;
        mrun1 = mn1;
#pragma unroll
        for (int b = 0; b < 8; b++) {
            oacc[b][0] *= sc0; oacc[b][1] *= sc0;
            oacc[b][2] *= sc1; oacc[b][3] *= sc1;
        }

#pragma unroll
        for (int ks = 0; ks < 4; ks++) {
            uint32_t aH[4], aL[4];
            split2(sacc[2 * ks][0],     sacc[2 * ks][1],     aH[0], aL[0]);
            split2(sacc[2 * ks][2],     sacc[2 * ks][3],     aH[1], aL[1]);
            split2(sacc[2 * ks + 1][0], sacc[2 * ks + 1][1], aH[2], aL[2]);
            split2(sacc[2 * ks + 1][2], sacc[2 * ks + 1][3], aH[3], aL[3]);
#pragma unroll
            for (int db = 0; db < 4; db++) {
                uint32_t bh[4], bl[4];
                ldsm4(bh, smem_u32(&Vc[(db * 16 + lrow) * VLD + ks * 16 + lcol]));
                ldsm4(bl, smem_u32(&Vc[((64 + db * 16) + lrow) * VLD + ks * 16 + lcol]));
                mma16816(oacc[2 * db + 0], aH, bh[0], bh[2]);
                mma16816(oacc[2 * db + 1], aH, bh[1], bh[3]);
                mma16816(oacc[2 * db + 0], aL, bh[0], bh[2]);
                mma16816(oacc[2 * db + 1], aL, bh[1], bh[3]);
                mma16816(oacc[2 * db + 0], aH, bl[0], bl[2]);
                mma16816(oacc[2 * db + 1], aH, bl[1], bl[3]);
            }
        }
    }

    float inv0 = 1.0f / lrun0, inv1 = 1.0f / lrun1;
#pragma unroll
    for (int b = 0; b < 8; b++) {
        int d = b * 8 + (lane & 3) * 2;
        uint32_t hi0, lo0, hi1, lo1;
        split2(oacc[b][0] * inv0, oacc[b][1] * inv0, hi0, lo0);
        split2(oacc[b][2] * inv1, oacc[b][3] * inv1, hi1, lo1);
        __nv_bfloat16* d0 = oc + (size_t)qg0 * KC + h * HD + d;
        __nv_bfloat16* d1 = oc + (size_t)qg1 * KC + h * HD + d;
        *(uint32_t*)(d0)        = hi0;
        *(uint32_t*)(d0 + 1024) = hi0;
        *(uint32_t*)(d0 + 2048) = lo0;
        *(uint32_t*)(d1)        = hi1;
        *(uint32_t*)(d1 + 1024) = hi1;
        *(uint32_t*)(d1 + 2048) = lo1;
    }
}

// ---------------------------------------------------------------------------
// Launch
// ---------------------------------------------------------------------------
extern "C" void kernel_launch(void* const* d_in, const int* in_sizes, int n_in,
                              void* d_out, int out_size)
{
    (void)in_sizes; (void)n_in; (void)out_size;

    const float* x = (const float*)d_in[0];
    const float* W[4] = {(const float*)d_in[1], (const float*)d_in[2],
                         (const float*)d_in[3], (const float*)d_in[4]};
    float* out = (float*)d_out;

    float* qkv;
    __nv_bfloat16 *xc, *oc, *wc, *qc, *kc, *vt;
    cudaGetSymbolAddress((void**)&qkv, g_qkv);
    cudaGetSymbolAddress((void**)&xc, g_xc);
    cudaGetSymbolAddress((void**)&oc, g_oc);
    cudaGetSymbolAddress((void**)&wc, g_wc);
    cudaGetSymbolAddress((void**)&qc, g_qc);
    cudaGetSymbolAddress((void**)&kc, g_kc);
    cudaGetSymbolAddress((void**)&vt, g_vt);

    cudaFuncSetAttribute(gemm_mma, cudaFuncAttributeMaxDynamicSharedMemorySize, GEMM_SMEM);
    cudaFuncSetAttribute(swa_mma_kernel, cudaFuncAttributeMaxDynamicSharedMemorySize, SWA_SMEM);

    const int nx = S_LEN * DIM;
    const int nw = DIM * DIM;

    split3_kernel<<<nx / 4 / 256, 256>>>(x, xc, nx);
    split3_w_kernel<<<dim3(nw / 4 / 256, 4), 256>>>(W[0], W[1], W[2], W[3], wc);

    // fused QKV projection: N = 3072
    gemm_mma<<<dim3(S_LEN / BM, 3 * DIM / BN), 128, GEMM_SMEM>>>(xc, wc, qkv, 3 * DIM);

    rope_split_kernel<<<dim3(S_LEN / 64, NH), 256>>>(qkv, qc, kc, vt);

    swa_mma_kernel<<<dim3(S_LEN / 64, NH), 128, SWA_SMEM>>>(qc, kc, vt, oc);

    // output projection: N = 1024
    gemm_mma<<<dim3(S_LEN / BM, DIM / BN), 128, GEMM_SMEM>>>(
        oc, wc + (size_t)3 * DIM * KC, out, DIM);
}